// round 12
// baseline (speedup 1.0000x reference)
#include <cuda_runtime.h>
#include <cstdint>

#define B_   8
#define N_   64
#define NUM_CLASSES 81
#define C_   86
#define NLEV 5
#define NROWS 248
#define MAXE 64
#define WUNITS 32336      // channel-row units per batch

__constant__ int   c_H[NLEV]       = {128, 64, 32, 16, 8};
__constant__ float c_ps[NLEV]      = {0.0078125f, 0.015625f, 0.03125f, 0.0625f, 0.125f};
__constant__ float c_invps[NLEV]   = {128.0f, 64.0f, 32.0f, 16.0f, 8.0f};
__constant__ float c_th0[NLEV]     = {0.0078125f, 0.0625f, 0.125f, 0.25f, 0.5f};
__constant__ float c_th1[NLEV]     = {0.0625f, 0.125f, 0.25f, 0.5f, 1.0f};
__constant__ size_t c_base[NLEV]   = {0ull, 11272192ull, 14090240ull, 14794752ull, 14970880ull};
__constant__ int   c_wubase[NLEV]  = {0, 22016, 27520, 30272, 31648};
__constant__ int   c_wlg[NLEV]     = {8, 6, 5, 4, 3};     // log2(row-units per channel)
__constant__ int   c_rowbase[NLEV] = {0, 128, 192, 224, 240};

struct __align__(16) Ent {
    unsigned int box, label;
    unsigned long long m0, m1;
};

// scratch (no allocation allowed)
__device__ float4     g_sboxes[B_][N_];
__device__ ulonglong2 g_covA[B_ * NROWS];
__device__ int        g_nE[B_ * NROWS];
__device__ Ent        g_ent[B_ * NROWS][MAXE];

// ---------------- K1: sort + per-row cov/winner-entry extraction ----------------
__global__ __launch_bounds__(256)
void prep_kernel(const float* __restrict__ boxes,
                 const int* __restrict__ labels) {
    const int b   = blockIdx.y;
    const int tid = threadIdx.x;
    __shared__ float  s_area[N_];
    __shared__ float4 s_sb[N_];
    __shared__ int    s_sl[N_];

    float4 w0;
    int lab0 = 0;
    if (tid < N_) {
        const float* bx = boxes + ((size_t)b * N_ + tid) * 4;
        w0 = make_float4(bx[0], bx[1], bx[2], bx[3]);
        lab0 = labels[(size_t)b * N_ + tid];
        s_area[tid] = (w0.z - w0.x) * (w0.w - w0.y);
    }
    __syncthreads();
    if (tid < N_) {
        float a = s_area[tid];
        int rank = 0;
#pragma unroll
        for (int j = 0; j < N_; j++) {
            float aj = s_area[j];
            rank += (aj > a) || (aj == a && j < tid);   // stable descending
        }
        s_sb[rank] = w0;
        s_sl[rank] = lab0;
    }
    __syncthreads();

    if (blockIdx.x == 0 && tid < N_) g_sboxes[b][tid] = s_sb[tid];

    const int lane = tid & 31;
    const int rid  = blockIdx.x * 8 + (tid >> 5);   // 0..247, exact
    int lev, y;
    if      (rid < 128) { lev = 0; y = rid; }
    else if (rid < 192) { lev = 1; y = rid - 128; }
    else if (rid < 224) { lev = 2; y = rid - 192; }
    else if (rid < 240) { lev = 3; y = rid - 224; }
    else                { lev = 4; y = rid - 240; }

    const int   H     = c_H[lev];
    const float ps    = c_ps[lev];
    const float invps = c_invps[lev];
    const float th0   = c_th0[lev];
    const float th1   = c_th1[lev];
    const float t0m   = th0 * 0.999f;
    const float t1m   = th1 * 1.001f;
    const float my    = ((float)y + 0.5f) * ps;

    // ---- cov + cand masks (2 boxes per lane) ----
    unsigned long long cv0 = 0ull, cv1 = 0ull, cand = 0ull;
#pragma unroll
    for (int t = 0; t < 2; t++) {
        const int n = lane + t * 32;
        float4 w = s_sb[n];
        if (my >= w.y && my <= w.w) {
            float md = fmaxf(w.z - w.x, w.w - w.y);
            if (md > t0m && 0.5f * md <= t1m) cand |= 1ull << n;

            int xlo = (int)ceilf(w.x * invps - 0.5f);
            if (((float)(xlo - 1) + 0.5f) * ps >= w.x) xlo--;
            else if (((float)xlo + 0.5f) * ps < w.x)  xlo++;
            int xhi = (int)floorf(w.z * invps - 0.5f);
            if (((float)(xhi + 1) + 0.5f) * ps <= w.z) xhi++;
            else if (((float)xhi + 0.5f) * ps > w.z)   xhi--;
            if (xlo < 0) xlo = 0;
            if (xhi > H - 1) xhi = H - 1;
            if (xlo <= xhi) {
                int l0 = xlo < 64 ? xlo : 64;
                int h0 = (xhi + 1) < 64 ? (xhi + 1) : 64;
                if (h0 > l0)
                    cv0 |= ((h0 == 64) ? ~0ull : ((1ull << h0) - 1)) & ~((1ull << l0) - 1);
                int l1 = xlo - 64 > 0 ? xlo - 64 : 0;
                int h1 = xhi + 1 - 64 > 0 ? xhi + 1 - 64 : 0;
                if (h1 > l1)
                    cv1 |= ((h1 == 64) ? ~0ull : ((1ull << h1) - 1)) & ~((1ull << l1) - 1);
            }
        }
    }
#pragma unroll
    for (int off = 16; off > 0; off >>= 1) {
        cv0  |= __shfl_xor_sync(0xFFFFFFFFu, cv0,  off);
        cv1  |= __shfl_xor_sync(0xFFFFFFFFu, cv1,  off);
        cand |= __shfl_xor_sync(0xFFFFFFFFu, cand, off);
    }

    const int rg = b * NROWS + rid;

    // ---- per-pixel winners: lane owns px [4*lane, 4*lane+4) ----
    int win[4] = {-1, -1, -1, -1};
    float mx[4];
#pragma unroll
    for (int k = 0; k < 4; k++) mx[k] = ((float)(4 * lane + k) + 0.5f) * ps;
    {
        unsigned long long cc = cand;
        while (cc) {
            const int n = __ffsll((long long)cc) - 1;
            cc &= cc - 1;
            float4 w = s_sb[n];
            float t   = my - w.y;
            float bo  = w.w - my;
            float tbx = fmaxf(t, bo);
#pragma unroll
            for (int k = 0; k < 4; k++) {
                if (4 * lane + k < H) {
                    float l = mx[k] - w.x, rr = w.z - mx[k];
                    float mxv = fmaxf(fmaxf(l, rr), tbx);
                    if (fminf(l, rr) >= 0.0f && mxv > th0 && mxv <= th1) win[k] = n;
                }
            }
        }
    }

    // ---- entry extraction ----
    int nE = 0;
    {
        unsigned long long cc = cand;
        while (cc) {
            const int n = __ffsll((long long)cc) - 1;
            cc &= cc - 1;
            unsigned nib = 0;
#pragma unroll
            for (int k = 0; k < 4; k++) if (win[k] == n) nib |= 1u << k;
            unsigned long long m0 = (lane < 16) ? ((unsigned long long)nib << (4 * lane)) : 0ull;
            unsigned long long m1 = (lane >= 16) ? ((unsigned long long)nib << (4 * (lane - 16))) : 0ull;
#pragma unroll
            for (int off = 16; off > 0; off >>= 1) {
                m0 |= __shfl_xor_sync(0xFFFFFFFFu, m0, off);
                m1 |= __shfl_xor_sync(0xFFFFFFFFu, m1, off);
            }
            if (m0 | m1) {
                if (lane == 0) {
                    Ent e;
                    e.box = (unsigned)n;
                    e.label = (unsigned)s_sl[n];
                    e.m0 = m0; e.m1 = m1;
                    g_ent[rg][nE] = e;
                }
                nE++;
            }
        }
    }
    if (lane == 0) {
        g_nE[rg] = nE;
        ulonglong2 cv; cv.x = cv0; cv.y = cv1;
        g_covA[rg] = cv;
    }
}

// ---------------- K2: channel-row writer (memset-style + sparse patches) -------
__global__ __launch_bounds__(128)
void write_kernel(float* __restrict__ out) {
    const int b = blockIdx.y;
    const int local = blockIdx.x * 128 + threadIdx.x;
    if (local >= WUNITS) return;
    const int lev = local < 22016 ? 0 : local < 27520 ? 1 : local < 30272 ? 2
                  : local < 31648 ? 3 : 4;
    const int rem = local - c_wubase[lev];
    const int lg  = c_wlg[lev];
    const int ch  = rem >> lg;
    const int r   = rem & ((1 << lg) - 1);

    const int H  = c_H[lev];
    const int HH = H * H;
    int y, p0, n4;
    if (lev == 0) { y = r >> 1; p0 = (r & 1) << 6; n4 = 16; }
    else          { y = r;      p0 = 0;            n4 = H >> 2; }

    const int rg = b * NROWS + c_rowbase[lev] + y;
    const int nE = g_nE[rg];                     // early cached load

    float* bp = out + c_base[lev] + (size_t)b * ((size_t)C_ * HH)
                    + (size_t)ch * HH + (size_t)y * H + p0;
    float4* o4 = reinterpret_cast<float4*>(bp);

    if (ch == 5) {
        // background class 0: dense 1.0 where NOT covered
        ulonglong2 cv = g_covA[rg];
        unsigned long long w = p0 ? cv.y : cv.x;
#pragma unroll 16
        for (int i = 0; i < n4; i++) {
            float4 v;
            v.x = ((w >> (4 * i + 0)) & 1ull) ? 0.0f : 1.0f;
            v.y = ((w >> (4 * i + 1)) & 1ull) ? 0.0f : 1.0f;
            v.z = ((w >> (4 * i + 2)) & 1ull) ? 0.0f : 1.0f;
            v.w = ((w >> (4 * i + 3)) & 1ull) ? 0.0f : 1.0f;
            o4[i] = v;
        }
        for (int e = 0; e < nE; e++) {
            Ent E = g_ent[rg][e];
            if (E.label == 0u) {
                unsigned long long m = p0 ? E.m1 : E.m0;
                while (m) { int x = __ffsll((long long)m) - 1; m &= m - 1; bp[x] = 1.0f; }
            }
        }
        return;
    }

    // zero fill (contiguous, immediate-offset stores)
    const float4 z = make_float4(0.0f, 0.0f, 0.0f, 0.0f);
    if (n4 == 16) {
#pragma unroll
        for (int i = 0; i < 16; i++) o4[i] = z;
    } else if (n4 == 8) {
#pragma unroll
        for (int i = 0; i < 8; i++) o4[i] = z;
    } else if (n4 == 4) {
#pragma unroll
        for (int i = 0; i < 4; i++) o4[i] = z;
    } else {
#pragma unroll
        for (int i = 0; i < 2; i++) o4[i] = z;
    }

    if (nE == 0) return;

    if (ch >= 6) {
        const unsigned cls = (unsigned)(ch - 5);
        for (int e = 0; e < nE; e++) {
            Ent E = g_ent[rg][e];
            if (E.label == cls) {
                unsigned long long m = p0 ? E.m1 : E.m0;
                while (m) { int x = __ffsll((long long)m) - 1; m &= m - 1; bp[x] = 1.0f; }
            }
        }
        return;
    }

    // ch 0..4: reg / centerness values at winner pixels
    const float ps = c_ps[lev];
    const float my = ((float)y + 0.5f) * ps;
    for (int e = 0; e < nE; e++) {
        Ent E = g_ent[rg][e];
        unsigned long long m = p0 ? E.m1 : E.m0;
        if (!m) continue;
        float4 w = g_sboxes[b][E.box];
        while (m) {
            int x = __ffsll((long long)m) - 1; m &= m - 1;
            float mx = ((float)(p0 + x) + 0.5f) * ps;
            float l  = mx - w.x;
            float t  = my - w.y;
            float rr = w.z - mx;
            float bo = w.w - my;
            float v;
            if      (ch == 0) v = l;
            else if (ch == 1) v = t;
            else if (ch == 2) v = rr;
            else if (ch == 3) v = bo;
            else {
                float dx = fminf(l, rr),  Dx = fmaxf(l, rr);
                float dy = fminf(t, bo),  Dy = fmaxf(t, bo);
                float arg = (dx / (Dx != 0.0f ? Dx : 1.0f)) *
                            (dy / (Dy != 0.0f ? Dy : 1.0f));
                v = (arg > 0.0f) ? sqrtf(arg) : 0.0f;
            }
            bp[x] = v;
        }
    }
}

extern "C" void kernel_launch(void* const* d_in, const int* in_sizes, int n_in,
                              void* d_out, int out_size) {
    const float* boxes  = (const float*)d_in[0];
    const int*   labels = (const int*)d_in[1];
    float* out = (float*)d_out;

    dim3 pgrid(31, B_);
    prep_kernel<<<pgrid, 256>>>(boxes, labels);

    dim3 wgrid((WUNITS + 127) / 128, B_);   // 253 x 8 = 2024 blocks, single wave
    write_kernel<<<wgrid, 128>>>(out);
}

// round 13
// speedup vs baseline: 2.4271x; 2.4271x over previous
#include <cuda_runtime.h>
#include <cstdint>

#define B_   8
#define N_   64
#define NUM_CLASSES 81
#define C_   86
#define NLEV 5
#define NROWS 248
#define UNITS8_PER_B 43648                    // 8 slices x (HH/4) summed over levels
#define TOTAL_UNITS (B_ * UNITS8_PER_B)       // 349184
#define WBLK 128
#define WGRID 1480                            // ~10 blocks/SM, single resident wave

__constant__ int   c_H[NLEV]      = {128, 64, 32, 16, 8};
__constant__ float c_ps[NLEV]     = {0.0078125f, 0.015625f, 0.03125f, 0.0625f, 0.125f};
__constant__ float c_invps[NLEV]  = {128.0f, 64.0f, 32.0f, 16.0f, 8.0f};
__constant__ float c_th0[NLEV]    = {0.0078125f, 0.0625f, 0.125f, 0.25f, 0.5f};
__constant__ float c_th1[NLEV]    = {0.0625f, 0.125f, 0.25f, 0.5f, 1.0f};

// scratch (no allocation allowed)
__device__ float4             g_sboxes[B_][N_];
__device__ int                g_slabels[B_][N_];
__device__ unsigned long long g_cov[B_][NLEV][128][2];
__device__ unsigned long long g_cand[B_][NLEV][128];

// ---------------- K1: fused sort + per-row masks (validated R8-R11) ----------------
__global__ __launch_bounds__(256)
void prep_kernel(const float* __restrict__ boxes,
                 const int* __restrict__ labels) {
    const int b   = blockIdx.y;
    const int tid = threadIdx.x;
    __shared__ float  s_area[N_];
    __shared__ float4 s_sb[N_];
    __shared__ int    s_sl[N_];

    float4 w0;
    int lab0 = 0;
    if (tid < N_) {
        const float* bx = boxes + ((size_t)b * N_ + tid) * 4;
        w0 = make_float4(bx[0], bx[1], bx[2], bx[3]);
        lab0 = labels[(size_t)b * N_ + tid];
        s_area[tid] = (w0.z - w0.x) * (w0.w - w0.y);
    }
    __syncthreads();
    if (tid < N_) {
        float a = s_area[tid];
        int rank = 0;
#pragma unroll
        for (int j = 0; j < N_; j++) {
            float aj = s_area[j];
            rank += (aj > a) || (aj == a && j < tid);
        }
        s_sb[rank] = w0;
        s_sl[rank] = lab0;
    }
    __syncthreads();

    if (blockIdx.x == 0 && tid < N_) {
        g_sboxes[b][tid]  = s_sb[tid];
        g_slabels[b][tid] = s_sl[tid];
    }

    const int lane = tid & 31;
    const int rid  = blockIdx.x * 8 + (tid >> 5);
    if (rid >= NROWS) return;

    int lev, y;
    if      (rid < 128) { lev = 0; y = rid; }
    else if (rid < 192) { lev = 1; y = rid - 128; }
    else if (rid < 224) { lev = 2; y = rid - 192; }
    else if (rid < 240) { lev = 3; y = rid - 224; }
    else                { lev = 4; y = rid - 240; }

    const int   H     = c_H[lev];
    const float ps    = c_ps[lev];
    const float invps = c_invps[lev];
    const float t0m   = c_th0[lev] * 0.999f;
    const float t1m   = c_th1[lev] * 1.001f;
    const float my    = ((float)y + 0.5f) * ps;

    unsigned long long cv0 = 0ull, cv1 = 0ull, cand = 0ull;
#pragma unroll
    for (int t = 0; t < 2; t++) {
        const int n = lane + t * 32;
        float4 w = s_sb[n];
        if (my >= w.y && my <= w.w) {
            float md = fmaxf(w.z - w.x, w.w - w.y);
            if (md > t0m && 0.5f * md <= t1m) cand |= 1ull << n;

            int xlo = (int)ceilf(w.x * invps - 0.5f);
            if (((float)(xlo - 1) + 0.5f) * ps >= w.x) xlo--;
            else if (((float)xlo + 0.5f) * ps < w.x)  xlo++;
            int xhi = (int)floorf(w.z * invps - 0.5f);
            if (((float)(xhi + 1) + 0.5f) * ps <= w.z) xhi++;
            else if (((float)xhi + 0.5f) * ps > w.z)   xhi--;
            if (xlo < 0) xlo = 0;
            if (xhi > H - 1) xhi = H - 1;
            if (xlo <= xhi) {
                int l0 = xlo < 64 ? xlo : 64;
                int h0 = (xhi + 1) < 64 ? (xhi + 1) : 64;
                if (h0 > l0)
                    cv0 |= ((h0 == 64) ? ~0ull : ((1ull << h0) - 1)) & ~((1ull << l0) - 1);
                int l1 = xlo - 64 > 0 ? xlo - 64 : 0;
                int h1 = xhi + 1 - 64 > 0 ? xhi + 1 - 64 : 0;
                if (h1 > l1)
                    cv1 |= ((h1 == 64) ? ~0ull : ((1ull << h1) - 1)) & ~((1ull << l1) - 1);
            }
        }
    }
#pragma unroll
    for (int off = 16; off > 0; off >>= 1) {
        cv0  |= __shfl_xor_sync(0xFFFFFFFFu, cv0,  off);
        cv1  |= __shfl_xor_sync(0xFFFFFFFFu, cv1,  off);
        cand |= __shfl_xor_sync(0xFFFFFFFFu, cand, off);
    }
    if (lane == 0) {
        g_cov[b][lev][y][0] = cv0;
        g_cov[b][lev][y][1] = cv1;
        g_cand[b][lev][y]   = cand;
    }
}

// ---------------- templated unit worker: all level constants compile-time ----------
template <int LEV>
__device__ __forceinline__ void do_unit(float* __restrict__ out, int b, int local) {
    constexpr int    H    = (LEV == 0) ? 128 : (LEV == 1) ? 64 : (LEV == 2) ? 32
                          : (LEV == 3) ? 16 : 8;
    constexpr int    HH   = H * H;
    constexpr int    gsh  = (LEV == 0) ? 12 : (LEV == 1) ? 10 : (LEV == 2) ? 8
                          : (LEV == 3) ? 6 : 4;
    constexpr int    logH = (LEV == 0) ? 7 : (LEV == 1) ? 6 : (LEV == 2) ? 5
                          : (LEV == 3) ? 4 : 3;
    constexpr float  ps   = 1.0f / (float)H;
    constexpr float  th0  = (LEV == 0) ? 0.0078125f : (LEV == 1) ? 0.0625f
                          : (LEV == 2) ? 0.125f : (LEV == 3) ? 0.25f : 0.5f;
    constexpr float  th1  = (LEV == 0) ? 0.0625f : (LEV == 1) ? 0.125f
                          : (LEV == 2) ? 0.25f : (LEV == 3) ? 0.5f : 1.0f;
    constexpr size_t base = (LEV == 0) ? 0ull : (LEV == 1) ? 11272192ull
                          : (LEV == 2) ? 14090240ull : (LEV == 3) ? 14794752ull
                          : 14970880ull;
    constexpr size_t cs   = (size_t)HH;

    const int s = local >> gsh;                        // slice 0..7
    const int g = local & ((1 << gsh) - 1);

    const int gx4 = g << 2;
    const int y   = gx4 >> logH;
    const int x0  = gx4 & (H - 1);

    // metadata loads first (independent of the zero stores)
    unsigned long long cand = g_cand[b][LEV][y];
    const unsigned long long cov = (s == 0) ? g_cov[b][LEV][y][x0 >> 6] : 0ull;

    float* rowp = out + base + (size_t)b * (C_ * cs) + (size_t)y * H + x0;
    float* clsp = rowp + 5 * cs;
    const float4 z = make_float4(0.0f, 0.0f, 0.0f, 0.0f);

    // ---- phase 1: zero channels [11s, min(11s+11,86)) — immediate-offset stores --
    float* slicep = rowp + (size_t)(11 * s) * cs;
    if (s == 7) {
#pragma unroll
        for (int i = 0; i < 9; i++)
            *reinterpret_cast<float4*>(slicep + (size_t)i * cs) = z;
    } else {
#pragma unroll
        for (int i = 0; i < 11; i++)
            *reinterpret_cast<float4*>(slicep + (size_t)i * cs) = z;
    }

    // ---- phase 2: sparse values / patches ----
    const int sh = x0 & 63;
    if (cand == 0ull) {
        if (s == 0) {
#pragma unroll
            for (int k = 0; k < 4; k++)
                if (!((cov >> (sh + k)) & 1ull)) clsp[k] = 1.0f;   // background
        }
        return;
    }

    const float my = ((float)y + 0.5f) * ps;
    float mx[4];
#pragma unroll
    for (int k = 0; k < 4; k++) mx[k] = ((float)(x0 + k) + 0.5f) * ps;

    int win[4] = {-1, -1, -1, -1};
    while (cand) {
        const int n = __ffsll((long long)cand) - 1;
        cand &= cand - 1;
        float4 w = g_sboxes[b][n];
        float t   = my - w.y;
        float bo  = w.w - my;
        float tbx = fmaxf(t, bo);
#pragma unroll
        for (int k = 0; k < 4; k++) {
            float l = mx[k] - w.x, rr = w.z - mx[k];
            float mxv = fmaxf(fmaxf(l, rr), tbx);
            if (fminf(l, rr) >= 0.0f && mxv > th0 && mxv <= th1) win[k] = n;
        }
    }

    if (s == 0) {
        bool anyw = (win[0] >= 0) || (win[1] >= 0) || (win[2] >= 0) || (win[3] >= 0);
        if (anyw) {
            float rl[4], rt[4], rr_[4], rb[4], ce[4];
#pragma unroll
            for (int k = 0; k < 4; k++) {
                if (win[k] >= 0) {
                    float4 w = g_sboxes[b][win[k]];
                    float l  = mx[k] - w.x;
                    float t  = my    - w.y;
                    float rr = w.z - mx[k];
                    float bo = w.w - my;
                    rl[k] = l; rt[k] = t; rr_[k] = rr; rb[k] = bo;
                    float dx = fminf(l, rr),  Dx = fmaxf(l, rr);
                    float dy = fminf(t, bo),  Dy = fmaxf(t, bo);
                    float arg = (dx / (Dx != 0.0f ? Dx : 1.0f)) *
                                (dy / (Dy != 0.0f ? Dy : 1.0f));
                    ce[k] = (arg > 0.0f) ? sqrtf(arg) : 0.0f;
                } else {
                    rl[k] = rt[k] = rr_[k] = rb[k] = 0.0f;
                    ce[k] = 0.0f;
                }
            }
            *reinterpret_cast<float4*>(rowp + 0 * cs) = make_float4(rl[0], rl[1], rl[2], rl[3]);
            *reinterpret_cast<float4*>(rowp + 1 * cs) = make_float4(rt[0], rt[1], rt[2], rt[3]);
            *reinterpret_cast<float4*>(rowp + 2 * cs) = make_float4(rr_[0], rr_[1], rr_[2], rr_[3]);
            *reinterpret_cast<float4*>(rowp + 3 * cs) = make_float4(rb[0], rb[1], rb[2], rb[3]);
            *reinterpret_cast<float4*>(rowp + 4 * cs) = make_float4(ce[0], ce[1], ce[2], ce[3]);
        }
#pragma unroll
        for (int k = 0; k < 4; k++) {
            if (win[k] >= 0) {
                int lab = g_slabels[b][win[k]];
                if (lab < 6) clsp[(size_t)lab * cs + k] = 1.0f;    // cls 0..5 in slice 0
            } else if (!((cov >> (sh + k)) & 1ull)) {
                clsp[k] = 1.0f;
            }
        }
    } else {
        const int lo = 11 * s - 5;                                  // cls range of slice
        const int hi = (s == 7) ? NUM_CLASSES : lo + 11;
#pragma unroll
        for (int k = 0; k < 4; k++) {
            if (win[k] >= 0) {
                int lab = g_slabels[b][win[k]];
                if (lab >= lo && lab < hi) clsp[(size_t)lab * cs + k] = 1.0f;
            }
        }
    }
}

__device__ __forceinline__ void dispatch_unit(float* __restrict__ out, int u) {
    const int b = u / UNITS8_PER_B;                 // magic-mul constant div
    const int r = u - b * UNITS8_PER_B;
    if      (r < 32768) do_unit<0>(out, b, r);
    else if (r < 40960) do_unit<1>(out, b, r - 32768);
    else if (r < 43008) do_unit<2>(out, b, r - 40960);
    else if (r < 43520) do_unit<3>(out, b, r - 43008);
    else                do_unit<4>(out, b, r - 43520);
}

// ---------------- K2: grid-stride writer, single resident wave ----------------
__global__ __launch_bounds__(WBLK)
void fused_kernel(float* __restrict__ out) {
    int u = blockIdx.x * WBLK + threadIdx.x;
    dispatch_unit(out, u);                 // TOTAL_UNITS=349184, stride=189440
    u += WGRID * WBLK;
    if (u < TOTAL_UNITS) dispatch_unit(out, u);
}

extern "C" void kernel_launch(void* const* d_in, const int* in_sizes, int n_in,
                              void* d_out, int out_size) {
    const float* boxes  = (const float*)d_in[0];
    const int*   labels = (const int*)d_in[1];
    float* out = (float*)d_out;

    dim3 pgrid(31, B_);
    prep_kernel<<<pgrid, 256>>>(boxes, labels);

    fused_kernel<<<WGRID, WBLK>>>(out);
}

// round 14
// speedup vs baseline: 2.4819x; 1.0226x over previous
#include <cuda_runtime.h>
#include <cstdint>

#define B_   8
#define N_   64
#define NUM_CLASSES 81
#define C_   86

typedef unsigned long long u64;

template <int LEV>
__device__ __forceinline__ void block_work(
    const float* __restrict__ boxes, const int* __restrict__ labels,
    float* __restrict__ out, int b, int lbase,
    float4* s_sb, int* s_sl, float* s_area, u64* s_cand, u64 (*s_cov)[2])
{
    constexpr int    H    = (LEV == 0) ? 128 : (LEV == 1) ? 64 : (LEV == 2) ? 32
                          : (LEV == 3) ? 16 : 8;
    constexpr int    HH   = H * H;
    constexpr int    gsh  = (LEV == 0) ? 12 : (LEV == 1) ? 10 : (LEV == 2) ? 8
                          : (LEV == 3) ? 6 : 4;
    constexpr int    logH = (LEV == 0) ? 7 : (LEV == 1) ? 6 : (LEV == 2) ? 5
                          : (LEV == 3) ? 4 : 3;
    constexpr float  ps   = 1.0f / (float)H;
    constexpr float  invps= (float)H;
    constexpr float  th0  = (LEV == 0) ? 0.0078125f : (LEV == 1) ? 0.0625f
                          : (LEV == 2) ? 0.125f : (LEV == 3) ? 0.25f : 0.5f;
    constexpr float  th1  = (LEV == 0) ? 0.0625f : (LEV == 1) ? 0.125f
                          : (LEV == 2) ? 0.25f : (LEV == 3) ? 0.5f : 1.0f;
    constexpr size_t base = (LEV == 0) ? 0ull : (LEV == 1) ? 11272192ull
                          : (LEV == 2) ? 14090240ull : (LEV == 3) ? 14794752ull
                          : 14970880ull;
    constexpr size_t cs   = (size_t)HH;
    constexpr int    NR   = (LEV == 0) ? 4 : (LEV == 1) ? 8 : (LEV == 2) ? 16
                          : (LEV == 3) ? 16 : 8;   // rows this block touches

    const int tid = threadIdx.x;

    // ---- stage 1: stable descending-area sort into smem ----
    float4 w0;
    int lab0 = 0;
    if (tid < N_) {
        const float* bx = boxes + ((size_t)b * N_ + tid) * 4;
        w0 = make_float4(bx[0], bx[1], bx[2], bx[3]);
        lab0 = labels[(size_t)b * N_ + tid];
        s_area[tid] = (w0.z - w0.x) * (w0.w - w0.y);
    }
    __syncthreads();
    if (tid < N_) {
        float a = s_area[tid];
        int rank = 0;
#pragma unroll
        for (int j = 0; j < N_; j++) {
            float aj = s_area[j];
            rank += (aj > a) || (aj == a && j < tid);   // stable descending
        }
        s_sb[rank] = w0;
        s_sl[rank] = lab0;
    }
    __syncthreads();

    // ---- stage 2: per-row cand/cov masks (warp per row, validated logic) ----
    int y0;
    if (LEV <= 2) { int g0 = lbase & ((1 << gsh) - 1); y0 = (g0 << 2) >> logH; }
    else          { y0 = 0; }

    const int wid  = tid >> 5;
    const int lane = tid & 31;
#pragma unroll
    for (int ry = wid; ry < NR; ry += 4) {
        const int   y  = y0 + ry;
        const float my = ((float)y + 0.5f) * ps;
        u64 cv0 = 0ull, cv1 = 0ull, cand = 0ull;
#pragma unroll
        for (int t = 0; t < 2; t++) {
            const int n = lane + t * 32;
            float4 w = s_sb[n];
            if (my >= w.y && my <= w.w) {
                float md = fmaxf(w.z - w.x, w.w - w.y);
                if (md > th0 * 0.999f && 0.5f * md <= th1 * 1.001f) cand |= 1ull << n;

                // exact x-coverage: x s.t. (x+0.5)*ps in [w.x, w.z], with fixup
                int xlo = (int)ceilf(w.x * invps - 0.5f);
                if (((float)(xlo - 1) + 0.5f) * ps >= w.x) xlo--;
                else if (((float)xlo + 0.5f) * ps < w.x)  xlo++;
                int xhi = (int)floorf(w.z * invps - 0.5f);
                if (((float)(xhi + 1) + 0.5f) * ps <= w.z) xhi++;
                else if (((float)xhi + 0.5f) * ps > w.z)   xhi--;
                if (xlo < 0) xlo = 0;
                if (xhi > H - 1) xhi = H - 1;
                if (xlo <= xhi) {
                    int l0 = xlo < 64 ? xlo : 64;
                    int h0 = (xhi + 1) < 64 ? (xhi + 1) : 64;
                    if (h0 > l0)
                        cv0 |= ((h0 == 64) ? ~0ull : ((1ull << h0) - 1)) & ~((1ull << l0) - 1);
                    int l1 = xlo - 64 > 0 ? xlo - 64 : 0;
                    int h1 = xhi + 1 - 64 > 0 ? xhi + 1 - 64 : 0;
                    if (h1 > l1)
                        cv1 |= ((h1 == 64) ? ~0ull : ((1ull << h1) - 1)) & ~((1ull << l1) - 1);
                }
            }
        }
#pragma unroll
        for (int off = 16; off > 0; off >>= 1) {
            cv0  |= __shfl_xor_sync(0xFFFFFFFFu, cv0,  off);
            cv1  |= __shfl_xor_sync(0xFFFFFFFFu, cv1,  off);
            cand |= __shfl_xor_sync(0xFFFFFFFFu, cand, off);
        }
        if (lane == 0) {
            s_cand[ry]   = cand;
            s_cov[ry][0] = cv0;
            s_cov[ry][1] = cv1;
        }
    }
    __syncthreads();

    // ---- stage 3: unit write (validated R13 structure; metadata from smem) ----
    const int local = lbase + tid;
    const int s = local >> gsh;                 // slice 0..7
    const int g = local & ((1 << gsh) - 1);

    const int gx4 = g << 2;
    const int y   = gx4 >> logH;
    const int x0  = gx4 & (H - 1);

    u64 cand = s_cand[y - y0];
    const u64 cov = (s == 0) ? s_cov[y - y0][x0 >> 6] : 0ull;

    float* rowp = out + base + (size_t)b * (C_ * cs) + (size_t)y * H + x0;
    float* clsp = rowp + 5 * cs;
    const float4 z = make_float4(0.0f, 0.0f, 0.0f, 0.0f);

    // phase 1: zero channels [11s, min(11s+11,86))
    float* slicep = rowp + (size_t)(11 * s) * cs;
    if (s == 7) {
#pragma unroll
        for (int i = 0; i < 9; i++)
            *reinterpret_cast<float4*>(slicep + (size_t)i * cs) = z;
    } else {
#pragma unroll
        for (int i = 0; i < 11; i++)
            *reinterpret_cast<float4*>(slicep + (size_t)i * cs) = z;
    }

    // phase 2: sparse values / patches
    const int sh = x0 & 63;
    if (cand == 0ull) {
        if (s == 0) {
#pragma unroll
            for (int k = 0; k < 4; k++)
                if (!((cov >> (sh + k)) & 1ull)) clsp[k] = 1.0f;   // background
        }
        return;
    }

    const float my = ((float)y + 0.5f) * ps;
    float mx[4];
#pragma unroll
    for (int k = 0; k < 4; k++) mx[k] = ((float)(x0 + k) + 0.5f) * ps;

    int win[4] = {-1, -1, -1, -1};
    while (cand) {
        const int n = __ffsll((long long)cand) - 1;
        cand &= cand - 1;
        float4 w = s_sb[n];
        float t   = my - w.y;
        float bo  = w.w - my;
        float tbx = fmaxf(t, bo);
#pragma unroll
        for (int k = 0; k < 4; k++) {
            float l = mx[k] - w.x, rr = w.z - mx[k];
            float mxv = fmaxf(fmaxf(l, rr), tbx);
            if (fminf(l, rr) >= 0.0f && mxv > th0 && mxv <= th1) win[k] = n;
        }
    }

    if (s == 0) {
        bool anyw = (win[0] >= 0) || (win[1] >= 0) || (win[2] >= 0) || (win[3] >= 0);
        if (anyw) {
            float rl[4], rt[4], rr_[4], rb[4], ce[4];
#pragma unroll
            for (int k = 0; k < 4; k++) {
                if (win[k] >= 0) {
                    float4 w = s_sb[win[k]];
                    float l  = mx[k] - w.x;
                    float t  = my    - w.y;
                    float rr = w.z - mx[k];
                    float bo = w.w - my;
                    rl[k] = l; rt[k] = t; rr_[k] = rr; rb[k] = bo;
                    float dx = fminf(l, rr),  Dx = fmaxf(l, rr);
                    float dy = fminf(t, bo),  Dy = fmaxf(t, bo);
                    float arg = (dx / (Dx != 0.0f ? Dx : 1.0f)) *
                                (dy / (Dy != 0.0f ? Dy : 1.0f));
                    ce[k] = (arg > 0.0f) ? sqrtf(arg) : 0.0f;
                } else {
                    rl[k] = rt[k] = rr_[k] = rb[k] = 0.0f;
                    ce[k] = 0.0f;
                }
            }
            *reinterpret_cast<float4*>(rowp + 0 * cs) = make_float4(rl[0], rl[1], rl[2], rl[3]);
            *reinterpret_cast<float4*>(rowp + 1 * cs) = make_float4(rt[0], rt[1], rt[2], rt[3]);
            *reinterpret_cast<float4*>(rowp + 2 * cs) = make_float4(rr_[0], rr_[1], rr_[2], rr_[3]);
            *reinterpret_cast<float4*>(rowp + 3 * cs) = make_float4(rb[0], rb[1], rb[2], rb[3]);
            *reinterpret_cast<float4*>(rowp + 4 * cs) = make_float4(ce[0], ce[1], ce[2], ce[3]);
        }
#pragma unroll
        for (int k = 0; k < 4; k++) {
            if (win[k] >= 0) {
                int lab = s_sl[win[k]];
                if (lab < 6) clsp[(size_t)lab * cs + k] = 1.0f;    // cls 0..5 in slice 0
            } else if (!((cov >> (sh + k)) & 1ull)) {
                clsp[k] = 1.0f;
            }
        }
    } else {
        const int lo = 11 * s - 5;                                  // cls range of slice
        const int hi = (s == 7) ? NUM_CLASSES : lo + 11;
#pragma unroll
        for (int k = 0; k < 4; k++) {
            if (win[k] >= 0) {
                int lab = s_sl[win[k]];
                if (lab >= lo && lab < hi) clsp[(size_t)lab * cs + k] = 1.0f;
            }
        }
    }
}

// ---------------- single mega-kernel ----------------
// per batch: lev0 256 blocks, lev1 64, lev2 16, lev3 4, lev4 1  -> 341
__global__ __launch_bounds__(128)
void mega_kernel(const float* __restrict__ boxes,
                 const int* __restrict__ labels,
                 float* __restrict__ out) {
    __shared__ float4 s_sb[N_];
    __shared__ int    s_sl[N_];
    __shared__ float  s_area[N_];
    __shared__ u64    s_cand[16];
    __shared__ u64    s_cov[16][2];

    const int b   = blockIdx.y;
    const int blk = blockIdx.x;

    if (blk < 256)
        block_work<0>(boxes, labels, out, b, blk * 128,          s_sb, s_sl, s_area, s_cand, s_cov);
    else if (blk < 320)
        block_work<1>(boxes, labels, out, b, (blk - 256) * 128,  s_sb, s_sl, s_area, s_cand, s_cov);
    else if (blk < 336)
        block_work<2>(boxes, labels, out, b, (blk - 320) * 128,  s_sb, s_sl, s_area, s_cand, s_cov);
    else if (blk < 340)
        block_work<3>(boxes, labels, out, b, (blk - 336) * 128,  s_sb, s_sl, s_area, s_cand, s_cov);
    else
        block_work<4>(boxes, labels, out, b, 0,                  s_sb, s_sl, s_area, s_cand, s_cov);
}

extern "C" void kernel_launch(void* const* d_in, const int* in_sizes, int n_in,
                              void* d_out, int out_size) {
    const float* boxes  = (const float*)d_in[0];
    const int*   labels = (const int*)d_in[1];
    float* out = (float*)d_out;

    dim3 grid(341, B_);    // 2728 self-contained blocks, one launch
    mega_kernel<<<grid, 128>>>(boxes, labels, out);
}